// round 16
// baseline (speedup 1.0000x reference)
#include <cuda_runtime.h>
#include <cuda_bf16.h>
#include <cstdint>
#include <math.h>

#define Bb   2
#define Ll   2048
#define Dd   1024
#define Hh   16
#define HDh  64
#define NC   512
#define BLD  (Bb*Ll*Dd)     /* 4194304 */
#define NTOK (Bb*Hh*Ll)     /* 65536   */

// Intermediates
__device__ float g_q   [NTOK*HDh];
__device__ float g_k   [NTOK*HDh];
__device__ float g_attn[NTOK*HDh];
__device__ float g_lred[512];
__device__ float g_c2  [Hh*NC];
__device__ uint2 g_cbs    [Hh*NC*32];
__device__ uint2 g_khat_hl[(size_t)Bb*Hh*Ll*32];
__device__ uint2 g_vt     [(size_t)Bb*Hh*HDh*(Ll/2)];

__device__ __forceinline__ uint32_t bfpack(float e0, float e1) {
    uint32_t r;
    asm("cvt.rn.bf16x2.f32 %0, %1, %2;" : "=r"(r) : "f"(e1), "f"(e0));
    return r;
}
__device__ __forceinline__ float tob(float x) {
    return __bfloat162float(__float2bfloat16_rn(x));
}
__device__ __forceinline__ void mma_bf16(float* d, const uint32_t* a, const uint32_t* b) {
    asm volatile(
        "mma.sync.aligned.m16n8k16.row.col.f32.bf16.bf16.f32 "
        "{%0,%1,%2,%3},{%4,%5,%6,%7},{%8,%9},{%0,%1,%2,%3};"
        : "+f"(d[0]), "+f"(d[1]), "+f"(d[2]), "+f"(d[3])
        : "r"(a[0]), "r"(a[1]), "r"(a[2]), "r"(a[3]), "r"(b[0]), "r"(b[1]));
}

#define PITCH 12
#define PLANE (128*PITCH)
#define STG   (4*PLANE)
#define PD    136

// ===========================================================================
// 3xBF16 split GEMM body (modes 0/1/2) — unchanged
// ===========================================================================
__device__ __forceinline__ void
gemm_mma_body(const float* __restrict__ A, const float* __restrict__ W,
              float* __restrict__ out, int mode, int bx, int by,
              uint32_t* smem) {
    int tid  = threadIdx.x;
    int lane = tid & 31;
    int gid  = lane >> 2, tig = lane & 3;
    int warp = tid >> 5;
    int wm = (warp >> 1) * 32, wn = (warp & 1) * 64;
    int r0 = by * 128, n0 = bx * 128;

    float4 va[2], vb[2];

    auto ldA = [&](int kb) {
        #pragma unroll
        for (int j = 0; j < 2; j++) {
            int idx = tid + j*256;
            int m = idx >> 2, kq = (idx & 3) * 4;
            if (mode != 1) {
                va[j] = *(const float4*)(A + (size_t)(r0 + m)*Dd + kb + kq);
            } else {
                int r = r0 + m, b = r >> 11, l = r & 2047;
                int c0 = kb + kq;
                va[j] = *(const float4*)(g_attn +
                          (((size_t)(b*Hh + (c0 >> 6)))*Ll + l)*HDh + (c0 & 63));
            }
        }
    };
    auto ldB = [&](int kb) {
        #pragma unroll
        for (int j = 0; j < 2; j++) {
            int idx = tid + j*256;
            int n = idx >> 2, kq = (idx & 3) * 4;
            vb[j] = *(const float4*)(W + (size_t)(n0 + n)*Dd + kb + kq);
        }
    };
    auto splitStore = [&](float4 v, uint32_t* hiP, uint32_t* loP, int m, int kq) {
        float hx = tob(v.x), hy = tob(v.y), hz = tob(v.z), hw = tob(v.w);
        uint2 hiw = { bfpack(hx, hy), bfpack(hz, hw) };
        uint2 low = { bfpack(v.x - hx, v.y - hy), bfpack(v.z - hz, v.w - hw) };
        *(uint2*)&hiP[m*PITCH + (kq >> 1)] = hiw;
        *(uint2*)&loP[m*PITCH + (kq >> 1)] = low;
    };
    auto stAB = [&](int s) {
        uint32_t* base = smem + s*STG;
        #pragma unroll
        for (int j = 0; j < 2; j++) {
            int idx = tid + j*256;
            int m = idx >> 2, kq = (idx & 3) * 4;
            splitStore(va[j], base,           base + PLANE,   m, kq);
            splitStore(vb[j], base + 2*PLANE, base + 3*PLANE, m, kq);
        }
    };

    ldA(0); ldB(0);
    stAB(0);
    __syncthreads();

    float acc[2][8][4] = {};
    const int NIT = Dd / 16;
    for (int it = 0; it < NIT; it++) {
        int s = it & 1;
        if (it + 1 < NIT) { ldA((it+1)*16); ldB((it+1)*16); }
        const uint32_t* Ahi = smem + s*STG;
        const uint32_t* Alo = Ahi + PLANE;
        const uint32_t* Bhi = Ahi + 2*PLANE;
        const uint32_t* Blo = Ahi + 3*PLANE;

        uint32_t af[2][2][4];
        uint32_t bf[8][2][2];
        #pragma unroll
        for (int mt = 0; mt < 2; mt++) {
            int mr = wm + mt*16 + gid;
            af[mt][0][0] = Ahi[ mr     *PITCH + tig    ];
            af[mt][0][1] = Ahi[(mr + 8)*PITCH + tig    ];
            af[mt][0][2] = Ahi[ mr     *PITCH + tig + 4];
            af[mt][0][3] = Ahi[(mr + 8)*PITCH + tig + 4];
            af[mt][1][0] = Alo[ mr     *PITCH + tig    ];
            af[mt][1][1] = Alo[(mr + 8)*PITCH + tig    ];
            af[mt][1][2] = Alo[ mr     *PITCH + tig + 4];
            af[mt][1][3] = Alo[(mr + 8)*PITCH + tig + 4];
        }
        #pragma unroll
        for (int j = 0; j < 8; j++) {
            int nc = wn + j*8 + gid;
            bf[j][0][0] = Bhi[nc*PITCH + tig    ];
            bf[j][0][1] = Bhi[nc*PITCH + tig + 4];
            bf[j][1][0] = Blo[nc*PITCH + tig    ];
            bf[j][1][1] = Blo[nc*PITCH + tig + 4];
        }
        #pragma unroll
        for (int mt = 0; mt < 2; mt++)
            #pragma unroll
            for (int j = 0; j < 8; j++) {
                mma_bf16(acc[mt][j], af[mt][0], bf[j][0]);
                mma_bf16(acc[mt][j], af[mt][0], bf[j][1]);
                mma_bf16(acc[mt][j], af[mt][1], bf[j][0]);
            }

        if (it + 1 < NIT) stAB(s ^ 1);
        __syncthreads();
    }

    float* Ds = (float*)smem;
    #pragma unroll 1
    for (int half = 0; half < 2; half++) {
        __syncthreads();
        if (mode == 2) {
            if ((wm >> 6) == half) {
                int lr0 = wm - half*64;
                #pragma unroll
                for (int mt = 0; mt < 2; mt++)
                    #pragma unroll
                    for (int j = 0; j < 8; j++) {
                        int lr  = lr0 + mt*16 + gid;
                        int col = wn + j*8 + tig*2;
                        Ds[ col   *66 + lr    ] = acc[mt][j][0];
                        Ds[(col+1)*66 + lr    ] = acc[mt][j][1];
                        Ds[ col   *66 + lr + 8] = acc[mt][j][2];
                        Ds[(col+1)*66 + lr + 8] = acc[mt][j][3];
                    }
            }
            __syncthreads();
            int b = r0 >> 11, lb = r0 & 2047;
            int lpbase = (lb + half*64) >> 1;
            #pragma unroll
            for (int i = 0; i < 16; i++) {
                int idx = tid + i*256;
                int lp = idx & 31, c = idx >> 5;
                float2 v = *(const float2*)&Ds[c*66 + 2*lp];
                float hx = tob(v.x), hy = tob(v.y);
                uint2 o = { bfpack(hx, hy), bfpack(v.x - hx, v.y - hy) };
                int bh = b*Hh + (n0 >> 6) + (c >> 6);
                g_vt[((size_t)bh*HDh + (c & 63))*(Ll/2) + lpbase + lp] = o;
            }
            continue;
        }
        if ((wm >> 6) == half) {
            int lr0 = wm - half*64;
            #pragma unroll
            for (int mt = 0; mt < 2; mt++)
                #pragma unroll
                for (int j = 0; j < 8; j++) {
                    int lr  = lr0 + mt*16 + gid;
                    int col = wn + j*8 + tig*2;
                    *(float2*)&Ds[ lr     *PD + col] = make_float2(acc[mt][j][0], acc[mt][j][1]);
                    *(float2*)&Ds[(lr + 8)*PD + col] = make_float2(acc[mt][j][2], acc[mt][j][3]);
                }
        }
        __syncthreads();
        if (mode == 0) {
            int b = r0 >> 11, lb = r0 & 2047;
            #pragma unroll
            for (int i = 0; i < 8; i++) {
                int idx = tid + i*256;
                int lr = idx >> 5, c4 = (idx & 31) * 4;
                int e = n0 + c4, h = e >> 6, hd = e & 63;
                *(float4*)(out + (((size_t)(b*Hh + h))*Ll + lb + half*64 + lr)*HDh + hd)
                    = *(float4*)&Ds[lr*PD + c4];
            }
        } else {
            #pragma unroll
            for (int i = 0; i < 8; i++) {
                int idx = tid + i*256;
                int lr = idx >> 5, c4 = (idx & 31) * 4;
                *(float4*)(out + (size_t)(r0 + half*64 + lr)*Dd + n0 + c4)
                    = *(float4*)&Ds[lr*PD + c4];
            }
        }
    }
}

// ===========================================================================
// fp32 FFMA GEMM body — K projection (conflict-free, BIT-IDENTICAL)
// ===========================================================================
#define FP 132

__device__ __forceinline__ void
gemm_f32_body(const float* __restrict__ A, const float* __restrict__ W,
              float* __restrict__ out, int bx, int by, uint32_t* smemu) {
    float* As = (float*)smemu;
    float* Bs = As + 2*8*FP;

    int tid  = threadIdx.x;
    int lane = tid & 31;
    int warp = tid >> 5;
    int wy = warp >> 1, wx = warp & 1;
    int ay = lane >> 3, bxl = lane & 7;
    int r0 = by * 128, n0 = bx * 128;

    int ra = wy*32 + ay*4;
    int cb = wx*64 + bxl*4;

    int lm = tid >> 1;
    int lk = (tid & 1) * 4;
    float4 va, vb;

    auto ld = [&](int k0) {
        va = *(const float4*)(A + (size_t)(r0 + lm)*Dd + k0 + lk);
        vb = *(const float4*)(W + (size_t)(n0 + lm)*Dd + k0 + lk);
    };
    auto st = [&](int s) {
        float* Ap = As + s*8*FP;
        float* Bp = Bs + s*8*FP;
        Ap[(lk+0)*FP+lm]=va.x; Ap[(lk+1)*FP+lm]=va.y; Ap[(lk+2)*FP+lm]=va.z; Ap[(lk+3)*FP+lm]=va.w;
        Bp[(lk+0)*FP+lm]=vb.x; Bp[(lk+1)*FP+lm]=vb.y; Bp[(lk+2)*FP+lm]=vb.z; Bp[(lk+3)*FP+lm]=vb.w;
    };

    ld(0); st(0);
    __syncthreads();

    float acc[8][8] = {};
    const int NIT = Dd / 8;
    for (int it = 0; it < NIT; it++) {
        int s = it & 1;
        if (it + 1 < NIT) ld((it+1)*8);
        const float* Ap = As + s*8*FP;
        const float* Bp = Bs + s*8*FP;
        #pragma unroll
        for (int k = 0; k < 8; k++) {
            float4 a0 = *(const float4*)&Ap[k*FP + ra];
            float4 a1 = *(const float4*)&Ap[k*FP + ra + 16];
            float4 b0 = *(const float4*)&Bp[k*FP + cb];
            float4 b1 = *(const float4*)&Bp[k*FP + cb + 32];
            float ar[8] = {a0.x,a0.y,a0.z,a0.w,a1.x,a1.y,a1.z,a1.w};
            float br[8] = {b0.x,b0.y,b0.z,b0.w,b1.x,b1.y,b1.z,b1.w};
            #pragma unroll
            for (int i = 0; i < 8; i++)
                #pragma unroll
                for (int j = 0; j < 8; j++)
                    acc[i][j] += ar[i] * br[j];
        }
        if (it + 1 < NIT) st(s ^ 1);
        __syncthreads();
    }

    int b = r0 >> 11;
    #pragma unroll
    for (int i = 0; i < 8; i++) {
        int r = r0 + ra + (i < 4 ? i : 16 + i - 4);
        int l = r & 2047;
        #pragma unroll
        for (int jg = 0; jg < 2; jg++) {
            int e = n0 + cb + jg*32;
            int h = e >> 6, hd = e & 63;
            *(float4*)(out + (((size_t)(b*Hh + h))*Ll + l)*HDh + hd)
                = *(float4*)&acc[i][jg*4];
        }
    }
}

// ===========================================================================
// FUSED FRONT: 800 blocks — K | Q | V | codebook prep  (unchanged)
// ===========================================================================
__global__ void __launch_bounds__(256)
fused_front(const float* __restrict__ x,  const float* __restrict__ Wq,
            const float* __restrict__ Wk, const float* __restrict__ Wv,
            const float* __restrict__ cb) {
    __shared__ __align__(16) uint32_t smem[2*STG];
    int bid = blockIdx.x;
    if (bid < 256) {
        gemm_f32_body(x, Wk, g_k, bid & 7, bid >> 3, smem);
    } else if (bid < 512) {
        int bb = bid - 256;
        gemm_mma_body(x, Wq, g_q, 0, bb & 7, bb >> 3, smem);
    } else if (bid < 768) {
        int bb = bid - 512;
        gemm_mma_body(x, Wv, nullptr, 2, bb & 7, bb >> 3, smem);
    } else {
        int row = (bid - 768) * 256 + threadIdx.x;
        const float* cr = cb + (size_t)row * HDh;
        float s0 = 0.f, s1 = 0.f, s2 = 0.f, s3 = 0.f;
        #pragma unroll
        for (int d = 0; d < 64; d += 4) {
            float4 v = *(const float4*)(cr + d);
            float hx = tob(v.x), hy = tob(v.y), hz = tob(v.z), hw = tob(v.w);
            g_cbs[(size_t)row*32 + (d >> 1)    ] =
                make_uint2(bfpack(hx, hy), bfpack(v.x - hx, v.y - hy));
            g_cbs[(size_t)row*32 + (d >> 1) + 1] =
                make_uint2(bfpack(hz, hw), bfpack(v.z - hz, v.w - hw));
            s0 += v.x*v.x; s1 += v.y*v.y; s2 += v.z*v.z; s3 += v.w*v.w;
        }
        g_c2[row] = (s0 + s1) + (s2 + s3);
    }
}

// ===========================================================================
// VQ — math unchanged (exact shortcodes); Cs fill vectorized (float4)
// ===========================================================================
__global__ void __launch_bounds__(128)
vq_kernel(const float* __restrict__ codebook, float* __restrict__ dout,
          int out_size) {
    __shared__ float Ks[128][65];
    __shared__ float Cs[64][68];
    __shared__ float c2s[64];
    __shared__ int   bestS[128];
    __shared__ float red[128];

    int tid = threadIdx.x;
    int bh  = blockIdx.y;
    int h   = bh & (Hh - 1);
    int l0  = blockIdx.x * 128;
    size_t kbase = ((size_t)bh * Ll + l0) * HDh;

    for (int idx = tid; idx < 128*64; idx += 128)
        Ks[idx >> 6][idx & 63] = g_k[kbase + idx];
    __syncthreads();

    float kr[64];
    float k0a = 0.f, k1a = 0.f, k2a = 0.f, k3a = 0.f;
    #pragma unroll
    for (int d = 0; d < 64; d += 4) {
        kr[d]   = Ks[tid][d];   k0a += kr[d]  *kr[d];
        kr[d+1] = Ks[tid][d+1]; k1a += kr[d+1]*kr[d+1];
        kr[d+2] = Ks[tid][d+2]; k2a += kr[d+2]*kr[d+2];
        kr[d+3] = Ks[tid][d+3]; k3a += kr[d+3]*kr[d+3];
    }
    float k2 = (k0a + k1a) + (k2a + k3a);

    float best = 3.4e38f;
    int bestc = 0;
    for (int cc = 0; cc < NC; cc += 64) {
        __syncthreads();
        #pragma unroll
        for (int p = 0; p < 8; p++) {               // 1024 float4 / 128 thr
            int idx = tid + p*128;
            int c = idx >> 4, q4 = (idx & 15) * 4;
            *(float4*)&Cs[c][q4] =
                *(const float4*)(codebook + ((size_t)h*NC + cc + c)*HDh + q4);
        }
        if (tid < 64)
            c2s[tid] = g_c2[h*NC + cc + tid];
        __syncthreads();
        #pragma unroll 4
        for (int c = 0; c < 64; c++) {
            float p0=0,p1=0,p2=0,p3=0;
            #pragma unroll
            for (int d = 0; d < 64; d += 4) {
                float4 cv = *(const float4*)&Cs[c][d];
                p0 += kr[d]*cv.x; p1 += kr[d+1]*cv.y;
                p2 += kr[d+2]*cv.z; p3 += kr[d+3]*cv.w;
            }
            float dist = (k2 + c2s[c]) - 2.f*((p0+p1)+(p2+p3));
            if (dist < best) { best = dist; bestc = cc + c; }
        }
    }

    bestS[tid] = bestc;
    red[tid]   = best;
    __syncthreads();
    for (int s = 64; s > 0; s >>= 1) {
        if (tid < s) red[tid] += red[tid + s];
        __syncthreads();
    }
    if (tid == 0)
        g_lred[blockIdx.y * 16 + blockIdx.x] = red[0];
    if (out_size >= BLD + 2 + NTOK)
        dout[BLD + 2 + (size_t)bh*Ll + l0 + tid] = (float)bestc;

    for (int idx = tid; idx < 128*32; idx += 128) {
        int r = idx >> 5, pr = idx & 31;
        g_khat_hl[((size_t)bh*Ll + l0 + r)*32 + pr]
            = g_cbs[((size_t)h*NC + bestS[r])*32 + pr];
    }
}

__global__ void __launch_bounds__(512)
finalize_loss(float* dout, int out_size) {
    __shared__ float red[512];
    int tid = threadIdx.x;
    red[tid] = g_lred[tid];
    __syncthreads();
    for (int s = 256; s > 0; s >>= 1) {
        if (tid < s) red[tid] += red[tid + s];
        __syncthreads();
    }
    if (tid == 0 && out_size >= BLD + 2) {
        float v = red[0] * (1.0f / (float)NTOK);
        dout[BLD]     = v;
        dout[BLD + 1] = v;
    }
}

// ===========================================================================
// bf16x3 mma flash attention v3: 128 thr / 64 query rows, 32-KEY SUBTILES,
// Q fragments in smem. Targets 4 CTAs/SM (launch_bounds 128,4).
// ===========================================================================
#define KVP 36   /* K row pitch, uint2 */
#define VVP 20   /* V row pitch, uint2 (16 key-pairs + pad) */

__global__ void __launch_bounds__(128, 4)
attn_mma_kernel() {
    __shared__ uint2 Qsm[16*128];     // [kb*4+r][tid] (hi, lo) 16KB
    __shared__ uint2 Ksm[32*KVP];     // 9.2KB
    __shared__ uint2 Vsm[64*VVP];     // 10.2KB

    int tid  = threadIdx.x;
    int lane = tid & 31;
    int gid  = lane >> 2, tig = lane & 3;
    int warp = tid >> 5;
    int bh   = blockIdx.y;
    int i0   = ((int)gridDim.x - 1 - (int)blockIdx.x) * 64;   // heavy first
    int row_start = i0 + warp * 16;
    int r0g  = row_start + gid;
    size_t base = (size_t)bh * Ll * HDh;

    // ---- Q fragments (scaled, split) -> smem ----
    const float scale = 0.125f;
    #pragma unroll
    for (int kb = 0; kb < 4; kb++) {
        #pragma unroll
        for (int cc = 0; cc < 2; cc++)
            #pragma unroll
            for (int rr = 0; rr < 2; rr++) {
                int row = r0g + rr*8;
                int col = kb*16 + tig*2 + cc*8;
                float2 v = *(const float2*)(g_q + base + (size_t)row*HDh + col);
                v.x *= scale; v.y *= scale;
                float hx = tob(v.x), hy = tob(v.y);
                int r = cc*2 + rr;
                Qsm[(kb*4 + r)*128 + tid] =
                    make_uint2(bfpack(hx, hy), bfpack(v.x - hx, v.y - hy));
            }
    }
    __syncthreads();

    float of[8][4] = {};
    float m0 = -1e30f, m1 = -1e30f, l0 = 0.f, l1 = 0.f;

    const uint2* kh = g_khat_hl + (size_t)bh * Ll * 32;
    const uint2* vt = g_vt     + (size_t)bh * HDh * (Ll/2);

    for (int j0 = 0; j0 < i0 + 64; j0 += 32) {
        // K tile: 32 keys x 32 uint2
        #pragma unroll
        for (int p = 0; p < 8; p++) {
            int idx = tid + p*128;
            int key = idx >> 5, pr = idx & 31;
            Ksm[key*KVP + pr] = kh[(size_t)(j0 + key)*32 + pr];
        }
        // V tile: 64 hd x 16 key-pairs
        #pragma unroll
        for (int p = 0; p < 8; p++) {
            int idx = tid + p*128;
            int hd = idx >> 4, kp = idx & 15;
            Vsm[hd*VVP + kp] = vt[(size_t)hd*(Ll/2) + (j0 >> 1) + kp];
        }
        __syncthreads();

        if (j0 <= row_start + 15) {
            // ---- S = Q K^T  (16 x 32) ----
            float sc[4][4] = {};
            #pragma unroll
            for (int kb = 0; kb < 4; kb++) {
                uint2 q0 = Qsm[(kb*4 + 0)*128 + tid];
                uint2 q1 = Qsm[(kb*4 + 1)*128 + tid];
                uint2 q2 = Qsm[(kb*4 + 2)*128 + tid];
                uint2 q3 = Qsm[(kb*4 + 3)*128 + tid];
                uint32_t qh[4] = {q0.x, q1.x, q2.x, q3.x};
                uint32_t ql[4] = {q0.y, q1.y, q2.y, q3.y};
                #pragma unroll
                for (int nj = 0; nj < 4; nj++) {
                    uint2 b0 = Ksm[(nj*8+gid)*KVP + kb*8 + tig];
                    uint2 b1 = Ksm[(nj*8+gid)*KVP + kb*8 + tig + 4];
                    uint32_t bhr[2] = {b0.x, b1.x}, blr[2] = {b0.y, b1.y};
                    mma_bf16(sc[nj], qh, bhr);
                    mma_bf16(sc[nj], qh, blr);
                    mma_bf16(sc[nj], ql, bhr);
                }
            }

            // ---- causal mask (diagonal subtiles) ----
            if (j0 + 31 > row_start) {
                #pragma unroll
                for (int nj = 0; nj < 4; nj++)
                    #pragma unroll
                    for (int e = 0; e < 2; e++) {
                        int col = j0 + nj*8 + tig*2 + e;
                        if (col > r0g)     sc[nj][e]     = -1e30f;
                        if (col > r0g + 8) sc[nj][2 + e] = -1e30f;
                    }
            }

            // ---- online softmax update ----
            float tm0 = -1e30f, tm1 = -1e30f;
            #pragma unroll
            for (int nj = 0; nj < 4; nj++) {
                tm0 = fmaxf(tm0, fmaxf(sc[nj][0], sc[nj][1]));
                tm1 = fmaxf(tm1, fmaxf(sc[nj][2], sc[nj][3]));
            }
            tm0 = fmaxf(tm0, __shfl_xor_sync(0xffffffff, tm0, 1));
            tm0 = fmaxf(tm0, __shfl_xor_sync(0xffffffff, tm0, 2));
            tm1 = fmaxf(tm1, __shfl_xor_sync(0xffffffff, tm1, 1));
            tm1 = fmaxf(tm1, __shfl_xor_sync(0xffffffff, tm1, 2));

            float mn0 = fmaxf(m0, tm0), mn1 = fmaxf(m1, tm1);
            float cr0 = __expf(m0 - mn0), cr1 = __expf(m1 - mn1);
            float rs0 = 0.f, rs1 = 0.f;
            #pragma unroll
            for (int nj = 0; nj < 4; nj++) {
                sc[nj][0] = __expf(sc[nj][0] - mn0);
                sc[nj][1] = __expf(sc[nj][1] - mn0);
                sc[nj][2] = __expf(sc[nj][2] - mn1);
                sc[nj][3] = __expf(sc[nj][3] - mn1);
                rs0 += sc[nj][0] + sc[nj][1];
                rs1 += sc[nj][2] + sc[nj][3];
            }
            rs0 += __shfl_xor_sync(0xffffffff, rs0, 1);
            rs0 += __shfl_xor_sync(0xffffffff, rs0, 2);
            rs1 += __shfl_xor_sync(0xffffffff, rs1, 1);
            rs1 += __shfl_xor_sync(0xffffffff, rs1, 2);
            l0 = l0*cr0 + rs0;
            l1 = l1*cr1 + rs1;
            m0 = mn0; m1 = mn1;
            #pragma unroll
            for (int nj = 0; nj < 8; nj++) {
                of[nj][0] *= cr0; of[nj][1] *= cr0;
                of[nj][2] *= cr1; of[nj][3] *= cr1;
            }

            // ---- O += P V  (P frags straight from S accum; 2 k-steps) ----
            #pragma unroll
            for (int kb = 0; kb < 2; kb++) {
                float p00 = sc[2*kb][0],   p01 = sc[2*kb][1];
                float p10 = sc[2*kb][2],   p11 = sc[2*kb][3];
                float p20 = sc[2*kb+1][0], p21 = sc[2*kb+1][1];
                float p30 = sc[2*kb+1][2], p31 = sc[2*kb+1][3];
                float h00 = tob(p00), h01 = tob(p01), h10 = tob(p10), h11 = tob(p11);
                float h20 = tob(p20), h21 = tob(p21), h30 = tob(p30), h31 = tob(p31);
                uint32_t ph[4] = { bfpack(h00,h01), bfpack(h10,h11),
                                   bfpack(h20,h21), bfpack(h30,h31) };
                uint32_t pl[4] = { bfpack(p00-h00, p01-h01), bfpack(p10-h10, p11-h11),
                                   bfpack(p20-h20, p21-h21), bfpack(p30-h30, p31-h31) };
                #pragma unroll
                for (int nj = 0; nj < 8; nj++) {
                    uint2 b0 = Vsm[(nj*8+gid)*VVP + kb*8 + tig];
                    uint2 b1 = Vsm[(nj*8+gid)*VVP + kb*8 + tig + 4];
                    uint32_t vh[2] = {b0.x, b1.x}, vl[2] = {b0.y, b1.y};
                    mma_bf16(of[nj], ph, vh);
                    mma_bf16(of[nj], ph, vl);
                    mma_bf16(of[nj], pl, vh);
                }
            }
        }
        __syncthreads();
    }

    float inv0 = 1.0f / l0, inv1 = 1.0f / l1;
    #pragma unroll
    for (int nj = 0; nj < 8; nj++) {
        *(float2*)(g_attn + base + (size_t)r0g*HDh + nj*8 + tig*2)
            = make_float2(of[nj][0]*inv0, of[nj][1]*inv0);
        *(float2*)(g_attn + base + (size_t)(r0g+8)*HDh + nj*8 + tig*2)
            = make_float2(of[nj][2]*inv1, of[nj][3]*inv1);
    }
}

// Wo wrapper (mode 1)
__global__ void __launch_bounds__(256)
gemm_wo_kernel(const float* __restrict__ W, float* __restrict__ out) {
    __shared__ __align__(16) uint32_t smem[2*STG];
    gemm_mma_body(nullptr, W, out, 1, blockIdx.x, blockIdx.y, smem);
}

// ===========================================================================
extern "C" void kernel_launch(void* const* d_in, const int* in_sizes, int n_in,
                              void* d_out, int out_size) {
    const float* x  = (const float*)d_in[0];
    const float* Wq = (const float*)d_in[1];
    const float* Wk = (const float*)d_in[2];
    const float* Wv = (const float*)d_in[3];
    const float* Wo = (const float*)d_in[4];
    const float* cb = (const float*)d_in[5];
    float* out = (float*)d_out;

    fused_front<<<800, 256>>>(x, Wq, Wk, Wv, cb);
    vq_kernel<<<dim3(Ll/128, Bb*Hh), 128>>>(cb, out, out_size);
    finalize_loss<<<1, 512>>>(out, out_size);
    attn_mma_kernel<<<dim3(Ll/64, Bb*Hh), 128>>>();
    gemm_wo_kernel<<<dim3(Dd/128, (Bb*Ll)/128), 256>>>(Wo, out);
}

// round 17
// speedup vs baseline: 1.0483x; 1.0483x over previous
#include <cuda_runtime.h>
#include <cuda_bf16.h>
#include <cstdint>
#include <math.h>

#define Bb   2
#define Ll   2048
#define Dd   1024
#define Hh   16
#define HDh  64
#define NC   512
#define BLD  (Bb*Ll*Dd)     /* 4194304 */
#define NTOK (Bb*Hh*Ll)     /* 65536   */

// Intermediates
__device__ float g_q   [NTOK*HDh];
__device__ float g_k   [NTOK*HDh];
__device__ float g_attn[NTOK*HDh];
__device__ float g_lred[512];
__device__ float g_c2  [Hh*NC];
__device__ uint2 g_cbs    [Hh*NC*32];
__device__ uint2 g_khat_hl[(size_t)Bb*Hh*Ll*32];
__device__ uint2 g_vt     [(size_t)Bb*Hh*HDh*(Ll/2)];

__device__ __forceinline__ uint32_t bfpack(float e0, float e1) {
    uint32_t r;
    asm("cvt.rn.bf16x2.f32 %0, %1, %2;" : "=r"(r) : "f"(e1), "f"(e0));
    return r;
}
__device__ __forceinline__ float tob(float x) {
    return __bfloat162float(__float2bfloat16_rn(x));
}
__device__ __forceinline__ void mma_bf16(float* d, const uint32_t* a, const uint32_t* b) {
    asm volatile(
        "mma.sync.aligned.m16n8k16.row.col.f32.bf16.bf16.f32 "
        "{%0,%1,%2,%3},{%4,%5,%6,%7},{%8,%9},{%0,%1,%2,%3};"
        : "+f"(d[0]), "+f"(d[1]), "+f"(d[2]), "+f"(d[3])
        : "r"(a[0]), "r"(a[1]), "r"(a[2]), "r"(a[3]), "r"(b[0]), "r"(b[1]));
}
// packed fp32x2 FMA: two independent IEEE fp32 FMAs per instruction
__device__ __forceinline__ uint64_t packf2(float lo, float hi) {
    uint64_t r; asm("mov.b64 %0, {%1, %2};" : "=l"(r) : "f"(lo), "f"(hi)); return r;
}
__device__ __forceinline__ void ffma2(uint64_t& d, uint64_t a, uint64_t b) {
    asm("fma.rn.f32x2 %0, %1, %2, %0;" : "+l"(d) : "l"(a), "l"(b));
}
__device__ __forceinline__ float2 unpackf2(uint64_t v) {
    float lo, hi; asm("mov.b64 {%0, %1}, %2;" : "=f"(lo), "=f"(hi) : "l"(v));
    return make_float2(lo, hi);
}

#define PITCH 12
#define PLANE (128*PITCH)
#define STG   (4*PLANE)
#define PD    136

// ===========================================================================
// 3xBF16 split GEMM body (modes 0/1/2) — unchanged
// ===========================================================================
__device__ __forceinline__ void
gemm_mma_body(const float* __restrict__ A, const float* __restrict__ W,
              float* __restrict__ out, int mode, int bx, int by,
              uint32_t* smem) {
    int tid  = threadIdx.x;
    int lane = tid & 31;
    int gid  = lane >> 2, tig = lane & 3;
    int warp = tid >> 5;
    int wm = (warp >> 1) * 32, wn = (warp & 1) * 64;
    int r0 = by * 128, n0 = bx * 128;

    float4 va[2], vb[2];

    auto ldA = [&](int kb) {
        #pragma unroll
        for (int j = 0; j < 2; j++) {
            int idx = tid + j*256;
            int m = idx >> 2, kq = (idx & 3) * 4;
            if (mode != 1) {
                va[j] = *(const float4*)(A + (size_t)(r0 + m)*Dd + kb + kq);
            } else {
                int r = r0 + m, b = r >> 11, l = r & 2047;
                int c0 = kb + kq;
                va[j] = *(const float4*)(g_attn +
                          (((size_t)(b*Hh + (c0 >> 6)))*Ll + l)*HDh + (c0 & 63));
            }
        }
    };
    auto ldB = [&](int kb) {
        #pragma unroll
        for (int j = 0; j < 2; j++) {
            int idx = tid + j*256;
            int n = idx >> 2, kq = (idx & 3) * 4;
            vb[j] = *(const float4*)(W + (size_t)(n0 + n)*Dd + kb + kq);
        }
    };
    auto splitStore = [&](float4 v, uint32_t* hiP, uint32_t* loP, int m, int kq) {
        float hx = tob(v.x), hy = tob(v.y), hz = tob(v.z), hw = tob(v.w);
        uint2 hiw = { bfpack(hx, hy), bfpack(hz, hw) };
        uint2 low = { bfpack(v.x - hx, v.y - hy), bfpack(v.z - hz, v.w - hw) };
        *(uint2*)&hiP[m*PITCH + (kq >> 1)] = hiw;
        *(uint2*)&loP[m*PITCH + (kq >> 1)] = low;
    };
    auto stAB = [&](int s) {
        uint32_t* base = smem + s*STG;
        #pragma unroll
        for (int j = 0; j < 2; j++) {
            int idx = tid + j*256;
            int m = idx >> 2, kq = (idx & 3) * 4;
            splitStore(va[j], base,           base + PLANE,   m, kq);
            splitStore(vb[j], base + 2*PLANE, base + 3*PLANE, m, kq);
        }
    };

    ldA(0); ldB(0);
    stAB(0);
    __syncthreads();

    float acc[2][8][4] = {};
    const int NIT = Dd / 16;
    for (int it = 0; it < NIT; it++) {
        int s = it & 1;
        if (it + 1 < NIT) { ldA((it+1)*16); ldB((it+1)*16); }
        const uint32_t* Ahi = smem + s*STG;
        const uint32_t* Alo = Ahi + PLANE;
        const uint32_t* Bhi = Ahi + 2*PLANE;
        const uint32_t* Blo = Ahi + 3*PLANE;

        uint32_t af[2][2][4];
        uint32_t bf[8][2][2];
        #pragma unroll
        for (int mt = 0; mt < 2; mt++) {
            int mr = wm + mt*16 + gid;
            af[mt][0][0] = Ahi[ mr     *PITCH + tig    ];
            af[mt][0][1] = Ahi[(mr + 8)*PITCH + tig    ];
            af[mt][0][2] = Ahi[ mr     *PITCH + tig + 4];
            af[mt][0][3] = Ahi[(mr + 8)*PITCH + tig + 4];
            af[mt][1][0] = Alo[ mr     *PITCH + tig    ];
            af[mt][1][1] = Alo[(mr + 8)*PITCH + tig    ];
            af[mt][1][2] = Alo[ mr     *PITCH + tig + 4];
            af[mt][1][3] = Alo[(mr + 8)*PITCH + tig + 4];
        }
        #pragma unroll
        for (int j = 0; j < 8; j++) {
            int nc = wn + j*8 + gid;
            bf[j][0][0] = Bhi[nc*PITCH + tig    ];
            bf[j][0][1] = Bhi[nc*PITCH + tig + 4];
            bf[j][1][0] = Blo[nc*PITCH + tig    ];
            bf[j][1][1] = Blo[nc*PITCH + tig + 4];
        }
        #pragma unroll
        for (int mt = 0; mt < 2; mt++)
            #pragma unroll
            for (int j = 0; j < 8; j++) {
                mma_bf16(acc[mt][j], af[mt][0], bf[j][0]);
                mma_bf16(acc[mt][j], af[mt][0], bf[j][1]);
                mma_bf16(acc[mt][j], af[mt][1], bf[j][0]);
            }

        if (it + 1 < NIT) stAB(s ^ 1);
        __syncthreads();
    }

    float* Ds = (float*)smem;
    #pragma unroll 1
    for (int half = 0; half < 2; half++) {
        __syncthreads();
        if (mode == 2) {
            if ((wm >> 6) == half) {
                int lr0 = wm - half*64;
                #pragma unroll
                for (int mt = 0; mt < 2; mt++)
                    #pragma unroll
                    for (int j = 0; j < 8; j++) {
                        int lr  = lr0 + mt*16 + gid;
                        int col = wn + j*8 + tig*2;
                        Ds[ col   *66 + lr    ] = acc[mt][j][0];
                        Ds[(col+1)*66 + lr    ] = acc[mt][j][1];
                        Ds[ col   *66 + lr + 8] = acc[mt][j][2];
                        Ds[(col+1)*66 + lr + 8] = acc[mt][j][3];
                    }
            }
            __syncthreads();
            int b = r0 >> 11, lb = r0 & 2047;
            int lpbase = (lb + half*64) >> 1;
            #pragma unroll
            for (int i = 0; i < 16; i++) {
                int idx = tid + i*256;
                int lp = idx & 31, c = idx >> 5;
                float2 v = *(const float2*)&Ds[c*66 + 2*lp];
                float hx = tob(v.x), hy = tob(v.y);
                uint2 o = { bfpack(hx, hy), bfpack(v.x - hx, v.y - hy) };
                int bh = b*Hh + (n0 >> 6) + (c >> 6);
                g_vt[((size_t)bh*HDh + (c & 63))*(Ll/2) + lpbase + lp] = o;
            }
            continue;
        }
        if ((wm >> 6) == half) {
            int lr0 = wm - half*64;
            #pragma unroll
            for (int mt = 0; mt < 2; mt++)
                #pragma unroll
                for (int j = 0; j < 8; j++) {
                    int lr  = lr0 + mt*16 + gid;
                    int col = wn + j*8 + tig*2;
                    *(float2*)&Ds[ lr     *PD + col] = make_float2(acc[mt][j][0], acc[mt][j][1]);
                    *(float2*)&Ds[(lr + 8)*PD + col] = make_float2(acc[mt][j][2], acc[mt][j][3]);
                }
        }
        __syncthreads();
        if (mode == 0) {
            int b = r0 >> 11, lb = r0 & 2047;
            #pragma unroll
            for (int i = 0; i < 8; i++) {
                int idx = tid + i*256;
                int lr = idx >> 5, c4 = (idx & 31) * 4;
                int e = n0 + c4, h = e >> 6, hd = e & 63;
                *(float4*)(out + (((size_t)(b*Hh + h))*Ll + lb + half*64 + lr)*HDh + hd)
                    = *(float4*)&Ds[lr*PD + c4];
            }
        } else {
            #pragma unroll
            for (int i = 0; i < 8; i++) {
                int idx = tid + i*256;
                int lr = idx >> 5, c4 = (idx & 31) * 4;
                *(float4*)(out + (size_t)(r0 + half*64 + lr)*Dd + n0 + c4)
                    = *(float4*)&Ds[lr*PD + c4];
            }
        }
    }
}

// ===========================================================================
// fp32 GEMM body — K projection, conflict-free frags + PACKED fma.rn.f32x2.
// Each FFMA2 lane is an independent IEEE fp32 FMA; per-element k-chain
// (k=0..1023 ascending) unchanged -> BIT-IDENTICAL K output.
// ===========================================================================
#define FP 132

__device__ __forceinline__ void
gemm_f32_body(const float* __restrict__ A, const float* __restrict__ W,
              float* __restrict__ out, int bx, int by, uint32_t* smemu) {
    float* As = (float*)smemu;
    float* Bs = As + 2*8*FP;

    int tid  = threadIdx.x;
    int lane = tid & 31;
    int warp = tid >> 5;
    int wy = warp >> 1, wx = warp & 1;
    int ay = lane >> 3, bxl = lane & 7;
    int r0 = by * 128, n0 = bx * 128;

    int ra = wy*32 + ay*4;
    int cb = wx*64 + bxl*4;

    int lm = tid >> 1;
    int lk = (tid & 1) * 4;
    float4 va, vb;

    auto ld = [&](int k0) {
        va = *(const float4*)(A + (size_t)(r0 + lm)*Dd + k0 + lk);
        vb = *(const float4*)(W + (size_t)(n0 + lm)*Dd + k0 + lk);
    };
    auto st = [&](int s) {
        float* Ap = As + s*8*FP;
        float* Bp = Bs + s*8*FP;
        Ap[(lk+0)*FP+lm]=va.x; Ap[(lk+1)*FP+lm]=va.y; Ap[(lk+2)*FP+lm]=va.z; Ap[(lk+3)*FP+lm]=va.w;
        Bp[(lk+0)*FP+lm]=vb.x; Bp[(lk+1)*FP+lm]=vb.y; Bp[(lk+2)*FP+lm]=vb.z; Bp[(lk+3)*FP+lm]=vb.w;
    };

    ld(0); st(0);
    __syncthreads();

    uint64_t acc2[8][4];
    #pragma unroll
    for (int i = 0; i < 8; i++)
        #pragma unroll
        for (int jp = 0; jp < 4; jp++) acc2[i][jp] = packf2(0.f, 0.f);

    const int NIT = Dd / 8;
    for (int it = 0; it < NIT; it++) {
        int s = it & 1;
        if (it + 1 < NIT) ld((it+1)*8);
        const float* Ap = As + s*8*FP;
        const float* Bp = Bs + s*8*FP;
        #pragma unroll
        for (int k = 0; k < 8; k++) {
            float4 a0 = *(const float4*)&Ap[k*FP + ra];
            float4 a1 = *(const float4*)&Ap[k*FP + ra + 16];
            float4 b0 = *(const float4*)&Bp[k*FP + cb];
            float4 b1 = *(const float4*)&Bp[k*FP + cb + 32];
            uint64_t brp[4] = { packf2(b0.x, b0.y), packf2(b0.z, b0.w),
                                packf2(b1.x, b1.y), packf2(b1.z, b1.w) };
            float ar[8] = {a0.x,a0.y,a0.z,a0.w,a1.x,a1.y,a1.z,a1.w};
            #pragma unroll
            for (int i = 0; i < 8; i++) {
                uint64_t ad = packf2(ar[i], ar[i]);
                #pragma unroll
                for (int jp = 0; jp < 4; jp++)
                    ffma2(acc2[i][jp], ad, brp[jp]);
            }
        }
        if (it + 1 < NIT) st(s ^ 1);
        __syncthreads();
    }

    int b = r0 >> 11;
    #pragma unroll
    for (int i = 0; i < 8; i++) {
        int r = r0 + ra + (i < 4 ? i : 16 + i - 4);
        int l = r & 2047;
        #pragma unroll
        for (int jg = 0; jg < 2; jg++) {
            int e = n0 + cb + jg*32;
            int h = e >> 6, hd = e & 63;
            float2 p0 = unpackf2(acc2[i][jg*2]);
            float2 p1 = unpackf2(acc2[i][jg*2 + 1]);
            float4 o = make_float4(p0.x, p0.y, p1.x, p1.y);
            *(float4*)(out + (((size_t)(b*Hh + h))*Ll + l)*HDh + hd) = o;
        }
    }
}

// ===========================================================================
// FUSED FRONT: 800 blocks — K | Q | V | codebook prep
// ===========================================================================
__global__ void __launch_bounds__(256)
fused_front(const float* __restrict__ x,  const float* __restrict__ Wq,
            const float* __restrict__ Wk, const float* __restrict__ Wv,
            const float* __restrict__ cb) {
    __shared__ __align__(16) uint32_t smem[2*STG];
    int bid = blockIdx.x;
    if (bid < 256) {
        gemm_f32_body(x, Wk, g_k, bid & 7, bid >> 3, smem);
    } else if (bid < 512) {
        int bb = bid - 256;
        gemm_mma_body(x, Wq, g_q, 0, bb & 7, bb >> 3, smem);
    } else if (bid < 768) {
        int bb = bid - 512;
        gemm_mma_body(x, Wv, nullptr, 2, bb & 7, bb >> 3, smem);
    } else {
        int row = (bid - 768) * 256 + threadIdx.x;
        const float* cr = cb + (size_t)row * HDh;
        float s0 = 0.f, s1 = 0.f, s2 = 0.f, s3 = 0.f;
        #pragma unroll
        for (int d = 0; d < 64; d += 4) {
            float4 v = *(const float4*)(cr + d);
            float hx = tob(v.x), hy = tob(v.y), hz = tob(v.z), hw = tob(v.w);
            g_cbs[(size_t)row*32 + (d >> 1)    ] =
                make_uint2(bfpack(hx, hy), bfpack(v.x - hx, v.y - hy));
            g_cbs[(size_t)row*32 + (d >> 1) + 1] =
                make_uint2(bfpack(hz, hw), bfpack(v.z - hz, v.w - hw));
            s0 += v.x*v.x; s1 += v.y*v.y; s2 += v.z*v.z; s3 += v.w*v.w;
        }
        g_c2[row] = (s0 + s1) + (s2 + s3);
    }
}

// ===========================================================================
// VQ — math unchanged (exact shortcodes); float4 Cs fill
// ===========================================================================
__global__ void __launch_bounds__(128)
vq_kernel(const float* __restrict__ codebook, float* __restrict__ dout,
          int out_size) {
    __shared__ float Ks[128][65];
    __shared__ float Cs[64][68];
    __shared__ float c2s[64];
    __shared__ int   bestS[128];
    __shared__ float red[128];

    int tid = threadIdx.x;
    int bh  = blockIdx.y;
    int h   = bh & (Hh - 1);
    int l0  = blockIdx.x * 128;
    size_t kbase = ((size_t)bh * Ll + l0) * HDh;

    for (int idx = tid; idx < 128*64; idx += 128)
        Ks[idx >> 6][idx & 63] = g_k[kbase + idx];
    __syncthreads();

    float kr[64];
    float k0a = 0.f, k1a = 0.f, k2a = 0.f, k3a = 0.f;
    #pragma unroll
    for (int d = 0; d < 64; d += 4) {
        kr[d]   = Ks[tid][d];   k0a += kr[d]  *kr[d];
        kr[d+1] = Ks[tid][d+1]; k1a += kr[d+1]*kr[d+1];
        kr[d+2] = Ks[tid][d+2]; k2a += kr[d+2]*kr[d+2];
        kr[d+3] = Ks[tid][d+3]; k3a += kr[d+3]*kr[d+3];
    }
    float k2 = (k0a + k1a) + (k2a + k3a);

    float best = 3.4e38f;
    int bestc = 0;
    for (int cc = 0; cc < NC; cc += 64) {
        __syncthreads();
        #pragma unroll
        for (int p = 0; p < 8; p++) {
            int idx = tid + p*128;
            int c = idx >> 4, q4 = (idx & 15) * 4;
            *(float4*)&Cs[c][q4] =
                *(const float4*)(codebook + ((size_t)h*NC + cc + c)*HDh + q4);
        }
        if (tid < 64)
            c2s[tid] = g_c2[h*NC + cc + tid];
        __syncthreads();
        #pragma unroll 4
        for (int c = 0; c < 64; c++) {
            float p0=0,p1=0,p2=0,p3=0;
            #pragma unroll
            for (int d = 0; d < 64; d += 4) {
                float4 cv = *(const float4*)&Cs[c][d];
                p0 += kr[d]*cv.x; p1 += kr[d+1]*cv.y;
                p2 += kr[d+2]*cv.z; p3 += kr[d+3]*cv.w;
            }
            float dist = (k2 + c2s[c]) - 2.f*((p0+p1)+(p2+p3));
            if (dist < best) { best = dist; bestc = cc + c; }
        }
    }

    bestS[tid] = bestc;
    red[tid]   = best;
    __syncthreads();
    for (int s = 64; s > 0; s >>= 1) {
        if (tid < s) red[tid] += red[tid + s];
        __syncthreads();
    }
    if (tid == 0)
        g_lred[blockIdx.y * 16 + blockIdx.x] = red[0];
    if (out_size >= BLD + 2 + NTOK)
        dout[BLD + 2 + (size_t)bh*Ll + l0 + tid] = (float)bestc;

    for (int idx = tid; idx < 128*32; idx += 128) {
        int r = idx >> 5, pr = idx & 31;
        g_khat_hl[((size_t)bh*Ll + l0 + r)*32 + pr]
            = g_cbs[((size_t)h*NC + bestS[r])*32 + pr];
    }
}

__global__ void __launch_bounds__(512)
finalize_loss(float* dout, int out_size) {
    __shared__ float red[512];
    int tid = threadIdx.x;
    red[tid] = g_lred[tid];
    __syncthreads();
    for (int s = 256; s > 0; s >>= 1) {
        if (tid < s) red[tid] += red[tid + s];
        __syncthreads();
    }
    if (tid == 0 && out_size >= BLD + 2) {
        float v = red[0] * (1.0f / (float)NTOK);
        dout[BLD]     = v;
        dout[BLD + 1] = v;
    }
}

// ===========================================================================
// bf16x3 mma flash attention — ROUND-13 VERSION (proven 240us, bit-exact):
// 128 threads / 64 query rows, 64-key tiles, Q in registers.
// ===========================================================================
#define KVP 36

__global__ void __launch_bounds__(128)
attn_mma_kernel() {
    __shared__ uint2 Ksm[64*KVP];
    __shared__ uint2 Vsm[64*KVP];

    int tid  = threadIdx.x;
    int lane = tid & 31;
    int gid  = lane >> 2, tig = lane & 3;
    int warp = tid >> 5;
    int bh   = blockIdx.y;
    int i0   = ((int)gridDim.x - 1 - (int)blockIdx.x) * 64;
    int row_start = i0 + warp * 16;
    int r0g  = row_start + gid;
    size_t base = (size_t)bh * Ll * HDh;

    const float scale = 0.125f;
    uint32_t qh[4][4], ql[4][4];
    #pragma unroll
    for (int kb = 0; kb < 4; kb++) {
        #pragma unroll
        for (int cc = 0; cc < 2; cc++)
            #pragma unroll
            for (int rr = 0; rr < 2; rr++) {
                int row = r0g + rr*8;
                int col = kb*16 + tig*2 + cc*8;
                float2 v = *(const float2*)(g_q + base + (size_t)row*HDh + col);
                v.x *= scale; v.y *= scale;
                float hx = tob(v.x), hy = tob(v.y);
                int r = cc*2 + rr;
                qh[kb][r] = bfpack(hx, hy);
                ql[kb][r] = bfpack(v.x - hx, v.y - hy);
            }
    }

    float of[8][4] = {};
    float m0 = -1e30f, m1 = -1e30f, l0 = 0.f, l1 = 0.f;

    const uint2* kh = g_khat_hl + (size_t)bh * Ll * 32;
    const uint2* vt = g_vt     + (size_t)bh * HDh * (Ll/2);

    for (int j0 = 0; j0 < i0 + 64; j0 += 64) {
        #pragma unroll
        for (int p = 0; p < 16; p++) {
            int idx = tid + p*128;
            int key = idx >> 5, pr = idx & 31;
            Ksm[key*KVP + pr] = kh[(size_t)(j0 + key)*32 + pr];
        }
        #pragma unroll
        for (int p = 0; p < 16; p++) {
            int idx = tid + p*128;
            int hd = idx >> 5, kp = idx & 31;
            Vsm[hd*KVP + kp] = vt[(size_t)hd*(Ll/2) + (j0 >> 1) + kp];
        }
        __syncthreads();

        if (j0 <= row_start + 15) {
            float sc[8][4] = {};
            #pragma unroll
            for (int kb = 0; kb < 4; kb++)
                #pragma unroll
                for (int nj = 0; nj < 8; nj++) {
                    uint2 b0 = Ksm[(nj*8+gid)*KVP + kb*8 + tig];
                    uint2 b1 = Ksm[(nj*8+gid)*KVP + kb*8 + tig + 4];
                    uint32_t bhr[2] = {b0.x, b1.x}, blr[2] = {b0.y, b1.y};
                    mma_bf16(sc[nj], qh[kb], bhr);
                    mma_bf16(sc[nj], qh[kb], blr);
                    mma_bf16(sc[nj], ql[kb], bhr);
                }

            if (j0 + 63 > row_start) {
                #pragma unroll
                for (int nj = 0; nj < 8; nj++)
                    #pragma unroll
                    for (int e = 0; e < 2; e++) {
                        int col = j0 + nj*8 + tig*2 + e;
                        if (col > r0g)     sc[nj][e]     = -1e30f;
                        if (col > r0g + 8) sc[nj][2 + e] = -1e30f;
                    }
            }

            float tm0 = -1e30f, tm1 = -1e30f;
            #pragma unroll
            for (int nj = 0; nj < 8; nj++) {
                tm0 = fmaxf(tm0, fmaxf(sc[nj][0], sc[nj][1]));
                tm1 = fmaxf(tm1, fmaxf(sc[nj][2], sc[nj][3]));
            }
            tm0 = fmaxf(tm0, __shfl_xor_sync(0xffffffff, tm0, 1));
            tm0 = fmaxf(tm0, __shfl_xor_sync(0xffffffff, tm0, 2));
            tm1 = fmaxf(tm1, __shfl_xor_sync(0xffffffff, tm1, 1));
            tm1 = fmaxf(tm1, __shfl_xor_sync(0xffffffff, tm1, 2));

            float mn0 = fmaxf(m0, tm0), mn1 = fmaxf(m1, tm1);
            float cr0 = __expf(m0 - mn0), cr1 = __expf(m1 - mn1);
            float rs0 = 0.f, rs1 = 0.f;
            #pragma unroll
            for (int nj = 0; nj < 8; nj++) {
                sc[nj][0] = __expf(sc[nj][0] - mn0);
                sc[nj][1] = __expf(sc[nj][1] - mn0);
                sc[nj][2] = __expf(sc[nj][2] - mn1);
                sc[nj][3] = __expf(sc[nj][3] - mn1);
                rs0 += sc[nj][0] + sc[nj][1];
                rs1 += sc[nj][2] + sc[nj][3];
            }
            rs0 += __shfl_xor_sync(0xffffffff, rs0, 1);
            rs0 += __shfl_xor_sync(0xffffffff, rs0, 2);
            rs1 += __shfl_xor_sync(0xffffffff, rs1, 1);
            rs1 += __shfl_xor_sync(0xffffffff, rs1, 2);
            l0 = l0*cr0 + rs0;
            l1 = l1*cr1 + rs1;
            m0 = mn0; m1 = mn1;
            #pragma unroll
            for (int nj = 0; nj < 8; nj++) {
                of[nj][0] *= cr0; of[nj][1] *= cr0;
                of[nj][2] *= cr1; of[nj][3] *= cr1;
            }

            #pragma unroll
            for (int kb = 0; kb < 4; kb++) {
                float p00 = sc[2*kb][0],   p01 = sc[2*kb][1];
                float p10 = sc[2*kb][2],   p11 = sc[2*kb][3];
                float p20 = sc[2*kb+1][0], p21 = sc[2*kb+1][1];
                float p30 = sc[2*kb+1][2], p31 = sc[2*kb+1][3];
                float h00 = tob(p00), h01 = tob(p01), h10 = tob(p10), h11 = tob(p11);
                float h20 = tob(p20), h21 = tob(p21), h30 = tob(p30), h31 = tob(p31);
                uint32_t ph[4] = { bfpack(h00,h01), bfpack(h10,h11),
                                   bfpack(h20,h21), bfpack(h30,h31) };
                uint32_t pl[4] = { bfpack(p00-h00, p01-h01), bfpack(p10-h10, p11-h11),
                                   bfpack(p20-h20, p21-h21), bfpack(p30-h30, p31-h31) };
                #pragma unroll
                for (int nj = 0; nj < 8; nj++) {
                    uint2 b0 = Vsm[(nj*8+gid)*KVP + kb*8 + tig];
                    uint2 b1 = Vsm[(nj*8+gid)*KVP + kb*8 + tig + 4];
                    uint32_t vh[2] = {b0.x, b1.x}, vl[2] = {b0.y, b1.y};
                    mma_bf16(of[nj], ph, vh);
                    mma_bf16(of[nj], ph, vl);
                    mma_bf16(of[nj], pl, vh);
                }
            }
        }
        __syncthreads();
    }

    float inv0 = 1.0f / l0, inv1 = 1.0f / l1;
    #pragma unroll
    for (int nj = 0; nj < 8; nj++) {
        *(float2*)(g_attn + base + (size_t)r0g*HDh + nj*8 + tig*2)
            = make_float2(of[nj][0]*inv0, of[nj][1]*inv0);
        *(float2*)(g_attn + base + (size_t)(r0g+8)*HDh + nj*8 + tig*2)
            = make_float2(of[nj][2]*inv1, of[nj][3]*inv1);
    }
}

// Wo wrapper (mode 1)
__global__ void __launch_bounds__(256)
gemm_wo_kernel(const float* __restrict__ W, float* __restrict__ out) {
    __shared__ __align__(16) uint32_t smem[2*STG];
    gemm_mma_body(nullptr, W, out, 1, blockIdx.x, blockIdx.y, smem);
}

// ===========================================================================
extern "C" void kernel_launch(void* const* d_in, const int* in_sizes, int n_in,
                              void* d_out, int out_size) {
    const float* x  = (const float*)d_in[0];
    const float* Wq = (const float*)d_in[1];
    const float* Wk = (const float*)d_in[2];
    const float* Wv = (const float*)d_in[3];
    const float* Wo = (const float*)d_in[4];
    const float* cb = (const float*)d_in[5];
    float* out = (float*)d_out;

    fused_front<<<800, 256>>>(x, Wq, Wk, Wv, cb);
    vq_kernel<<<dim3(Ll/128, Bb*Hh), 128>>>(cb, out, out_size);
    finalize_loss<<<1, 512>>>(out, out_size);
    attn_mma_kernel<<<dim3(Ll/64, Bb*Hh), 128>>>();
    gemm_wo_kernel<<<dim3(Dd/128, (Bb*Ll)/128), 256>>>(Wo, out);
}